// round 14
// baseline (speedup 1.0000x reference)
#include <cuda_runtime.h>
#include <math.h>

#define BB    4
#define NATN  1024
#define K_TAB 16384
#define S_LO  (-2.0f)
#define S_HI  (12.0f)

typedef unsigned long long ull;

// scratch: DR descriptors, G-table, type-sorted atom list
__device__ float g_DR[(size_t)BB * NATN * 1600];
__device__ float g_tab[2 * K_TAB * 100];       // 13.1 MB, [nt][knot][m]
__device__ int   g_sorted_n[1032];

// ---------------- packed f32x2 helpers (SASS FFMA2) ----------------
__device__ __forceinline__ ull pack2(float lo, float hi)
{
    ull r;
    asm("mov.b64 %0, {%1, %2};" : "=l"(r) : "f"(lo), "f"(hi));
    return r;
}
__device__ __forceinline__ void unpack2(ull v, float& lo, float& hi)
{
    asm("mov.b64 {%0, %1}, %2;" : "=f"(lo), "=f"(hi) : "l"(v));
}
__device__ __forceinline__ ull ffma2(ull a, ull b, ull c)
{
    ull d;
    asm("fma.rn.f32x2 %0, %1, %2, %3;" : "=l"(d) : "l"(a), "l"(b), "l"(c));
    return d;
}

// Exact-path lean tanh: 1 - 2*rcp(exp(2x)+1). Rel err ~1e-6, branch-free.
__device__ __forceinline__ float fast_tanh(float x)
{
    float e = __expf(2.0f * x);
    float r;
    asm("rcp.approx.f32 %0, %1;" : "=f"(r) : "f"(e + 1.0f));
    return fmaf(-2.0f, r, 1.0f);
}

// ---------------------------------------------------------------------------
// Kernel 0: deterministic partition of n-indices by atom type (single block)
// ---------------------------------------------------------------------------
__global__ void sort_kernel(const int* __restrict__ tmap)
{
    __shared__ int sa[1024], sb[1024];
    int tid = threadIdx.x;
    int myt = tmap[tid];
    sa[tid] = (myt == 0) ? 1 : 0;
    __syncthreads();
    int* cur = sa; int* nxt = sb;
    for (int off = 1; off < 1024; off <<= 1) {
        int v = cur[tid];
        if (tid >= off) v += cur[tid - off];
        __syncthreads();
        nxt[tid] = v;
        __syncthreads();
        int* tpp = cur; cur = nxt; nxt = tpp;
    }
    int scan0 = cur[tid];
    int cnt0  = cur[1023];

    g_sorted_n[tid] = -1;
    if (tid < 8) g_sorted_n[1024 + tid] = -1;
    __syncthreads();

    if (myt == 0) {
        g_sorted_n[scan0 - 1] = tid;
    } else {
        int base1 = ((cnt0 + 3) >> 2) << 2;
        g_sorted_n[base1 + tid - scan0] = tid;
    }
}

// ---------------------------------------------------------------------------
// Kernel 1: build G-table. G_nt(s) = embedding-MLP(concat[s, nf_nt]).
// ---------------------------------------------------------------------------
__global__ void __launch_bounds__(256) build_tab_kernel(
    const float* __restrict__ tvec,
    const float* __restrict__ tW0, const float* __restrict__ tb0,
    const float* __restrict__ eW0, const float* __restrict__ eb0,
    const float* __restrict__ eW1, const float* __restrict__ eb1,
    const float* __restrict__ eW2, const float* __restrict__ eb2)
{
    __shared__ float sW1[1250], sB1[50], sW2[5000], sBias[50], sW0c[25], sB2[100];
    int tid = threadIdx.x;

    for (int i = tid; i < 1250; i += 256) sW1[i] = eW1[i];
    for (int i = tid; i < 50;   i += 256) sB1[i] = eb1[i];
    for (int i = tid; i < 5000; i += 256) sW2[i] = eW2[i];
    for (int i = tid; i < 100;  i += 256) sB2[i] = eb2[i];
    for (int i = tid; i < 25;   i += 256) sW0c[i] = eW0[i];   // eW0 row 0 (s coeff)

    if (tid < 50) {
        int tt = tid / 25, m = tid % 25;
        float tv[4];
        #pragma unroll
        for (int p = 0; p < 4; p++) tv[p] = tvec[tt * 4 + p];
        float bias = eb0[m];
        #pragma unroll
        for (int k = 0; k < 8; k++) {
            float acc = tb0[k];
            #pragma unroll
            for (int p = 0; p < 4; p++) acc += tv[p] * tW0[p * 8 + k];
            float nfk = fast_tanh(acc) + tv[k & 3];
            bias += nfk * eW0[(k + 1) * 25 + m];
        }
        sBias[tt * 25 + m] = bias;
    }
    __syncthreads();

    int idx = blockIdx.x * 256 + tid;       // 0 .. 2*K_TAB-1
    int t = idx >> 14;                      // K_TAB = 2^14
    int i = idx & (K_TAB - 1);
    float s = S_LO + (S_HI - S_LO) * ((float)i / (float)(K_TAB - 1));

    float h0[25];
    #pragma unroll
    for (int m = 0; m < 25; m++)
        h0[m] = fast_tanh(sBias[t * 25 + m] + s * sW0c[m]);

    float h1[50];
    #pragma unroll
    for (int m = 0; m < 50; m++) h1[m] = sB1[m];
    for (int k = 0; k < 25; k++) {
        float hk = h0[k];
        #pragma unroll
        for (int m = 0; m < 50; m++) h1[m] += hk * sW1[k * 50 + m];
    }
    #pragma unroll
    for (int m = 0; m < 50; m++)
        h1[m] = fast_tanh(h1[m]) + h0[(m < 25) ? m : (m - 25)];

    float* out = g_tab + (size_t)(t * K_TAB + i) * 100;
    for (int c = 0; c < 2; c++) {
        float acc[50];
        #pragma unroll
        for (int m = 0; m < 50; m++) acc[m] = sB2[c * 50 + m];
        for (int k = 0; k < 50; k++) {
            float hk = h1[k];
            #pragma unroll
            for (int m = 0; m < 50; m++) acc[m] += hk * sW2[k * 100 + c * 50 + m];
        }
        #pragma unroll
        for (int m = 0; m < 50; m++)
            out[c * 50 + m] = fast_tanh(acc[m]) + h1[m];
    }
}

// ---------------------------------------------------------------------------
// Kernel 2: embed via table interpolation + xyz + DR. One block = atom.
// ---------------------------------------------------------------------------
__global__ void __launch_bounds__(256) embed_kernel(
    const float4* __restrict__ imdr,
    const int*    __restrict__ tmap,
    const float4* __restrict__ davg,
    const float4* __restrict__ dstd)
{
    __shared__ int    sK[200];      // knot*100 (pre-scaled row offset)
    __shared__ float  sF[200];      // fraction
    __shared__ float4 sRi4[200];
    __shared__ float  sP[1024];     // partials: [jh][d][128]
    __shared__ float  sXYZ[400];

    int tid = threadIdx.x;
    int a = blockIdx.x;
    int n = a & 1023;
    int t = tmap[n];

    if (tid < 200) {
        int j = tid;
        float4 im = imdr[(size_t)a * 200 + j];
        float r = im.x;
        float invr = (r > 1e-5f) ? (1.0f / r) : 1.0f;
        float u  = (r - 0.5f) * (1.0f / 5.5f);
        float u2 = u * u;
        float smid = invr * (u * u2 * (-6.0f * u2 + 15.0f * u - 10.0f) + 1.0f);
        float srij = 0.0f;
        if (r > 0.0f && r < 0.5f)        srij = invr;
        else if (r >= 0.5f && r < 6.0f)  srij = smid;
        bool msk = fabsf(r) > 1e-5f;
        float v0 = srij;
        float v1 = msk ? srij * im.y * invr : 0.0f;
        float v2 = msk ? srij * im.z * invr : 0.0f;
        float v3 = msk ? srij * im.w * invr : 0.0f;
        float4 da = davg[t * 200 + j];
        float4 ds = dstd[t * 200 + j];
        v0 = (v0 - da.x) / ds.x;
        v1 = (v1 - da.y) / ds.y;
        v2 = (v2 - da.z) / ds.z;
        v3 = (v3 - da.w) / ds.w;
        sRi4[j] = make_float4(v0, v1, v2, v3);

        float pos = (v0 - S_LO) * ((float)(K_TAB - 1) / (S_HI - S_LO));
        pos = fminf(fmaxf(pos, 0.0f), (float)(K_TAB - 1));
        float kf = floorf(pos);
        int k = (int)kf;
        if (k > K_TAB - 2) k = K_TAB - 2;
        sK[j] = k * 100;
        sF[j] = pos - (float)k;
    }
    __syncthreads();

    int jh = tid >> 7;
    int mslot = tid & 127;
    if (mslot < 100) {
        const float* tb = g_tab + (size_t)jh * K_TAB * 100 + mslot;  // nt = jh
        int j0 = jh * 100;
        float a0 = 0.0f, a1 = 0.0f, a2 = 0.0f, a3 = 0.0f;
        #pragma unroll 4
        for (int jj = 0; jj < 100; jj++) {
            int j = j0 + jj;
            int ko = sK[j];
            float f = sF[j];
            float4 ri = sRi4[j];
            float t0 = __ldg(tb + ko);
            float t1 = __ldg(tb + ko + 100);
            float g = fmaf(f, t1 - t0, t0);
            a0 = fmaf(ri.x, g, a0);
            a1 = fmaf(ri.y, g, a1);
            a2 = fmaf(ri.z, g, a2);
            a3 = fmaf(ri.w, g, a3);
        }
        sP[jh * 512 +   0 + mslot] = a0;
        sP[jh * 512 + 128 + mslot] = a1;
        sP[jh * 512 + 256 + mslot] = a2;
        sP[jh * 512 + 384 + mslot] = a3;
    }
    __syncthreads();

    for (int i = tid; i < 400; i += 256) {
        int d = i / 100, m = i - d * 100;
        sXYZ[d * 100 + m] =
            (sP[d * 128 + m] + sP[512 + d * 128 + m]) * (1.0f / 200.0f);
    }
    __syncthreads();

    for (int idx = tid; idx < 1600; idx += 256) {
        int m = idx >> 4, q = idx & 15;
        float s = 0.0f;
        #pragma unroll
        for (int d = 0; d < 4; d++)
            s += sXYZ[d * 100 + m] * sXYZ[d * 100 + q];
        g_DR[(size_t)a * 1600 + idx] = s;
    }
}

// ---------------------------------------------------------------------------
// Kernel 3: fitting net, register-tiled GEMM (4 m x 4 rows / thread) with
// double-buffered weight prefetch (GK=8 -> 8 LDG.128 in flight).
// Per k: 1 LDS.128 (broadcast) + 8 FFMA2; weights prefetched a group ahead.
// Block = 16 rows (4 batches x 4 same-type n), 1 CTA/SM, 133120 B smem.
// ---------------------------------------------------------------------------
#define GK 8

// One k-step of the 4x4 tile
#define FIT_STEP(WREG, A4)                                                    \
    do {                                                                      \
        ull ap_;                                                              \
        ap_ = pack2((A4).x, (A4).x);                                          \
        acc[0][0] = ffma2(ap_, (WREG).x, acc[0][0]);                          \
        acc[0][1] = ffma2(ap_, (WREG).y, acc[0][1]);                          \
        ap_ = pack2((A4).y, (A4).y);                                          \
        acc[1][0] = ffma2(ap_, (WREG).x, acc[1][0]);                          \
        acc[1][1] = ffma2(ap_, (WREG).y, acc[1][1]);                          \
        ap_ = pack2((A4).z, (A4).z);                                          \
        acc[2][0] = ffma2(ap_, (WREG).x, acc[2][0]);                          \
        acc[2][1] = ffma2(ap_, (WREG).y, acc[2][1]);                          \
        ap_ = pack2((A4).w, (A4).w);                                          \
        acc[3][0] = ffma2(ap_, (WREG).x, acc[3][0]);                          \
        acc[3][1] = ffma2(ap_, (WREG).y, acc[3][1]);                          \
    } while (0)

// Pipelined layer mainloop: K total k's, weights at wp + k*240 (ulonglong2),
// activations at dr + k*4 (float4).
#define FIT_LAYER_LOOP(KTOT, WP, DR)                                          \
    do {                                                                      \
        ulonglong2 wb[2][GK];                                                 \
        _Pragma("unroll")                                                     \
        for (int q = 0; q < GK; q++)                                          \
            wb[0][q] = *(const ulonglong2*)((WP) + q * 240);                  \
        int cur = 0;                                                          \
        for (int k0 = 0; k0 < (KTOT); k0 += GK) {                             \
            int nxt = cur ^ 1;                                                \
            if (k0 + GK < (KTOT)) {                                           \
                _Pragma("unroll")                                             \
                for (int q = 0; q < GK; q++)                                  \
                    wb[nxt][q] =                                              \
                        *(const ulonglong2*)((WP) + (k0 + GK + q) * 240);     \
            }                                                                 \
            _Pragma("unroll")                                                 \
            for (int q = 0; q < GK; q++) {                                    \
                float4 a4_ = *(const float4*)((DR) + (k0 + q) * 4);           \
                FIT_STEP(wb[cur][q], a4_);                                    \
            }                                                                 \
            cur = nxt;                                                        \
        }                                                                     \
    } while (0)

__global__ void __launch_bounds__(256, 1) fit_kernel(
    const int*   __restrict__ tmap,
    const float* __restrict__ fW0, const float* __restrict__ fb0,
    const float* __restrict__ fW1, const float* __restrict__ fb1,
    const float* __restrict__ fW2, const float* __restrict__ fb2,
    const float* __restrict__ fWf, const float* __restrict__ fbf,
    float* __restrict__ out)
{
    extern __shared__ float sm[];
    float* sDR4 = sm;            // [b][k][s]: b*6400 + k*4 + s
    float* sHa4 = sm + 25600;    // [b][m][s]: b*960 + m*4 + s
    float* sHb4 = sm + 29440;

    int tid = threadIdx.x;
    int g = blockIdx.x;
    int nn[4];
    nn[0] = g_sorted_n[g * 4 + 0];
    nn[1] = g_sorted_n[g * 4 + 1];
    nn[2] = g_sorted_n[g * 4 + 2];
    nn[3] = g_sorted_n[g * 4 + 3];
    int firstn = (nn[0] >= 0) ? nn[0] : (nn[1] >= 0) ? nn[1]
               : (nn[2] >= 0) ? nn[2] : nn[3];
    if (firstn < 0) return;
    int t = tmap[firstn];

    // stage DR: row = b*4 + s -> sDR4[b*6400 + k*4 + s]
    for (int idx = tid; idx < 16 * 1600; idx += 256) {
        int row = idx / 1600;
        int k   = idx - row * 1600;
        int b   = row >> 2, s = row & 3;
        int nv  = nn[s];
        float v = (nv >= 0) ? g_DR[((size_t)(b * 1024 + nv)) * 1600 + k] : 0.0f;
        sDR4[b * 6400 + k * 4 + s] = v;
    }
    __syncthreads();

    bool active = tid < 240;
    int mg = tid % 60;           // m block: 4*mg .. 4*mg+3
    int rg = tid / 60;           // row group == batch (0..3)

    ull  acc[4][2];              // [row r][m-pair]
    float prevA[4][4];
    float prevB[4][4];

    // ---- layer0: 1600 -> 240 ----
    if (active) {
        ulonglong2 b4 = *(const ulonglong2*)(fb0 + t * 240 + mg * 4);
        #pragma unroll
        for (int r = 0; r < 4; r++) { acc[r][0] = b4.x; acc[r][1] = b4.y; }
        const float* wp = fW0 + (size_t)t * 1600 * 240 + mg * 4;
        const float* dr = sDR4 + rg * 6400;
        FIT_LAYER_LOOP(1600, wp, dr);
        #pragma unroll
        for (int r = 0; r < 4; r++) {
            float v0, v1, v2, v3;
            unpack2(acc[r][0], v0, v1);
            unpack2(acc[r][1], v2, v3);
            prevA[r][0] = fast_tanh(v0);
            prevA[r][1] = fast_tanh(v1);
            prevA[r][2] = fast_tanh(v2);
            prevA[r][3] = fast_tanh(v3);
        }
        #pragma unroll
        for (int mi = 0; mi < 4; mi++) {
            float4 st = make_float4(prevA[0][mi], prevA[1][mi],
                                    prevA[2][mi], prevA[3][mi]);
            *(float4*)(sHa4 + rg * 960 + (mg * 4 + mi) * 4) = st;
        }
    }
    __syncthreads();

    // ---- layer1: 240 -> 240, resnet ----
    if (active) {
        ulonglong2 b4 = *(const ulonglong2*)(fb1 + t * 240 + mg * 4);
        #pragma unroll
        for (int r = 0; r < 4; r++) { acc[r][0] = b4.x; acc[r][1] = b4.y; }
        const float* wp = fW1 + (size_t)t * 240 * 240 + mg * 4;
        const float* dr = sHa4 + rg * 960;
        FIT_LAYER_LOOP(240, wp, dr);
        #pragma unroll
        for (int r = 0; r < 4; r++) {
            float v0, v1, v2, v3;
            unpack2(acc[r][0], v0, v1);
            unpack2(acc[r][1], v2, v3);
            prevB[r][0] = fast_tanh(v0) + prevA[r][0];
            prevB[r][1] = fast_tanh(v1) + prevA[r][1];
            prevB[r][2] = fast_tanh(v2) + prevA[r][2];
            prevB[r][3] = fast_tanh(v3) + prevA[r][3];
        }
        #pragma unroll
        for (int mi = 0; mi < 4; mi++) {
            float4 st = make_float4(prevB[0][mi], prevB[1][mi],
                                    prevB[2][mi], prevB[3][mi]);
            *(float4*)(sHb4 + rg * 960 + (mg * 4 + mi) * 4) = st;
        }
    }
    __syncthreads();

    // ---- layer2: 240 -> 240, resnet; result into sHa4 ----
    if (active) {
        ulonglong2 b4 = *(const ulonglong2*)(fb2 + t * 240 + mg * 4);
        #pragma unroll
        for (int r = 0; r < 4; r++) { acc[r][0] = b4.x; acc[r][1] = b4.y; }
        const float* wp = fW2 + (size_t)t * 240 * 240 + mg * 4;
        const float* dr = sHb4 + rg * 960;
        FIT_LAYER_LOOP(240, wp, dr);
        #pragma unroll
        for (int r = 0; r < 4; r++) {
            float v0, v1, v2, v3;
            unpack2(acc[r][0], v0, v1);
            unpack2(acc[r][1], v2, v3);
            prevA[r][0] = fast_tanh(v0) + prevB[r][0];
            prevA[r][1] = fast_tanh(v1) + prevB[r][1];
            prevA[r][2] = fast_tanh(v2) + prevB[r][2];
            prevA[r][3] = fast_tanh(v3) + prevB[r][3];
        }
        #pragma unroll
        for (int mi = 0; mi < 4; mi++) {
            float4 st = make_float4(prevA[0][mi], prevA[1][mi],
                                    prevA[2][mi], prevA[3][mi]);
            *(float4*)(sHa4 + rg * 960 + (mg * 4 + mi) * 4) = st;
        }
    }
    __syncthreads();

    // ---- final: h @ fWf + fbf (16 rows) ----
    if (tid < 16) {
        int b = tid >> 2, s = tid & 3;
        int nv = nn[s];
        if (nv >= 0) {
            float e = fbf[t];
            const float* Wf = fWf + t * 240;
            const float* h = sHa4 + b * 960 + s;
            float s0 = 0.0f;
            for (int k = 0; k < 240; k++)
                s0 += h[k * 4] * Wf[k];
            out[4 + b * 1024 + nv] = e + s0;
        }
    }
}

// ---------------------------------------------------------------------------
// Kernel 4: Etot = sum_n Ei (deterministic tree reduce, one block per batch)
// ---------------------------------------------------------------------------
__global__ void etot_kernel(float* __restrict__ out)
{
    __shared__ float red[256];
    int b = blockIdx.x, tid = threadIdx.x;
    float s = 0.0f;
    for (int i = tid; i < 1024; i += 256) s += out[4 + b * 1024 + i];
    red[tid] = s;
    __syncthreads();
    for (int off = 128; off > 0; off >>= 1) {
        if (tid < off) red[tid] += red[tid + off];
        __syncthreads();
    }
    if (tid == 0) out[b] = red[0];
}

// ---------------------------------------------------------------------------
extern "C" void kernel_launch(void* const* d_in, const int* in_sizes, int n_in,
                              void* d_out, int out_size)
{
    int off = (n_in >= 24) ? 0 : -1;   // nghost scalar may or may not materialize

    const int*    tmap = (const int*)   d_in[1];
    const float4* imdr = (const float4*)d_in[3];
    const float4* davg = (const float4*)d_in[5 + off];
    const float4* dstd = (const float4*)d_in[6 + off];
    const float*  tvec = (const float*) d_in[7 + off];
    const float*  tW0  = (const float*) d_in[8 + off];
    const float*  tb0  = (const float*) d_in[9 + off];
    const float*  eW0  = (const float*) d_in[10 + off];
    const float*  eb0  = (const float*) d_in[11 + off];
    const float*  eW1  = (const float*) d_in[12 + off];
    const float*  eb1  = (const float*) d_in[13 + off];
    const float*  eW2  = (const float*) d_in[14 + off];
    const float*  eb2  = (const float*) d_in[15 + off];
    const float*  fW0  = (const float*) d_in[16 + off];
    const float*  fb0  = (const float*) d_in[17 + off];
    const float*  fW1  = (const float*) d_in[18 + off];
    const float*  fb1  = (const float*) d_in[19 + off];
    const float*  fW2  = (const float*) d_in[20 + off];
    const float*  fb2  = (const float*) d_in[21 + off];
    const float*  fWf  = (const float*) d_in[22 + off];
    const float*  fbf  = (const float*) d_in[23 + off];
    float* out = (float*)d_out;

    cudaFuncSetAttribute(fit_kernel, cudaFuncAttributeMaxDynamicSharedMemorySize, 133120);

    sort_kernel<<<1, 1024>>>(tmap);
    build_tab_kernel<<<2 * K_TAB / 256, 256>>>(tvec, tW0, tb0, eW0, eb0,
                                               eW1, eb1, eW2, eb2);
    embed_kernel<<<4096, 256>>>(imdr, tmap, davg, dstd);
    fit_kernel<<<258, 256, 133120>>>(tmap, fW0, fb0, fW1, fb1, fW2, fb2,
                                     fWf, fbf, out);
    etot_kernel<<<4, 256>>>(out);
}

// round 15
// speedup vs baseline: 1.6994x; 1.6994x over previous
#include <cuda_runtime.h>
#include <math.h>

#define BB    4
#define NATN  1024
#define K_TAB 16384
#define S_LO  (-2.0f)
#define S_HI  (12.0f)

typedef unsigned long long ull;

// scratch: DR descriptors, G-table, type-sorted atom list
__device__ float g_DR[(size_t)BB * NATN * 1600];
__device__ float g_tab[2 * K_TAB * 100];       // 13.1 MB, [nt][knot][m]
__device__ int   g_sorted_n[1032];

// ---------------- packed f32x2 helpers (SASS FFMA2) ----------------
__device__ __forceinline__ ull pack2(float lo, float hi)
{
    ull r;
    asm("mov.b64 %0, {%1, %2};" : "=l"(r) : "f"(lo), "f"(hi));
    return r;
}
__device__ __forceinline__ void unpack2(ull v, float& lo, float& hi)
{
    asm("mov.b64 {%0, %1}, %2;" : "=f"(lo), "=f"(hi) : "l"(v));
}
__device__ __forceinline__ ull ffma2(ull a, ull b, ull c)
{
    ull d;
    asm("fma.rn.f32x2 %0, %1, %2, %3;" : "=l"(d) : "l"(a), "l"(b), "l"(c));
    return d;
}

// Exact-path lean tanh: 1 - 2*rcp(exp(2x)+1). Rel err ~1e-6, branch-free.
__device__ __forceinline__ float fast_tanh(float x)
{
    float e = __expf(2.0f * x);
    float r;
    asm("rcp.approx.f32 %0, %1;" : "=f"(r) : "f"(e + 1.0f));
    return fmaf(-2.0f, r, 1.0f);
}

// ---------------------------------------------------------------------------
// Kernel 0: deterministic partition of n-indices by atom type (single block)
// ---------------------------------------------------------------------------
__global__ void sort_kernel(const int* __restrict__ tmap)
{
    __shared__ int sa[1024], sb[1024];
    int tid = threadIdx.x;
    int myt = tmap[tid];
    sa[tid] = (myt == 0) ? 1 : 0;
    __syncthreads();
    int* cur = sa; int* nxt = sb;
    for (int off = 1; off < 1024; off <<= 1) {
        int v = cur[tid];
        if (tid >= off) v += cur[tid - off];
        __syncthreads();
        nxt[tid] = v;
        __syncthreads();
        int* tpp = cur; cur = nxt; nxt = tpp;
    }
    int scan0 = cur[tid];
    int cnt0  = cur[1023];

    g_sorted_n[tid] = -1;
    if (tid < 8) g_sorted_n[1024 + tid] = -1;
    __syncthreads();

    if (myt == 0) {
        g_sorted_n[scan0 - 1] = tid;
    } else {
        int base1 = ((cnt0 + 3) >> 2) << 2;
        g_sorted_n[base1 + tid - scan0] = tid;
    }
}

// ---------------------------------------------------------------------------
// Kernel 1: build G-table. G_nt(s) = embedding-MLP(concat[s, nf_nt]).
// ---------------------------------------------------------------------------
__global__ void __launch_bounds__(256) build_tab_kernel(
    const float* __restrict__ tvec,
    const float* __restrict__ tW0, const float* __restrict__ tb0,
    const float* __restrict__ eW0, const float* __restrict__ eb0,
    const float* __restrict__ eW1, const float* __restrict__ eb1,
    const float* __restrict__ eW2, const float* __restrict__ eb2)
{
    __shared__ float sW1[1250], sB1[50], sW2[5000], sBias[50], sW0c[25], sB2[100];
    int tid = threadIdx.x;

    for (int i = tid; i < 1250; i += 256) sW1[i] = eW1[i];
    for (int i = tid; i < 50;   i += 256) sB1[i] = eb1[i];
    for (int i = tid; i < 5000; i += 256) sW2[i] = eW2[i];
    for (int i = tid; i < 100;  i += 256) sB2[i] = eb2[i];
    for (int i = tid; i < 25;   i += 256) sW0c[i] = eW0[i];   // eW0 row 0 (s coeff)

    if (tid < 50) {
        int tt = tid / 25, m = tid % 25;
        float tv[4];
        #pragma unroll
        for (int p = 0; p < 4; p++) tv[p] = tvec[tt * 4 + p];
        float bias = eb0[m];
        #pragma unroll
        for (int k = 0; k < 8; k++) {
            float acc = tb0[k];
            #pragma unroll
            for (int p = 0; p < 4; p++) acc += tv[p] * tW0[p * 8 + k];
            float nfk = fast_tanh(acc) + tv[k & 3];
            bias += nfk * eW0[(k + 1) * 25 + m];
        }
        sBias[tt * 25 + m] = bias;
    }
    __syncthreads();

    int idx = blockIdx.x * 256 + tid;       // 0 .. 2*K_TAB-1
    int t = idx >> 14;                      // K_TAB = 2^14
    int i = idx & (K_TAB - 1);
    float s = S_LO + (S_HI - S_LO) * ((float)i / (float)(K_TAB - 1));

    float h0[25];
    #pragma unroll
    for (int m = 0; m < 25; m++)
        h0[m] = fast_tanh(sBias[t * 25 + m] + s * sW0c[m]);

    float h1[50];
    #pragma unroll
    for (int m = 0; m < 50; m++) h1[m] = sB1[m];
    for (int k = 0; k < 25; k++) {
        float hk = h0[k];
        #pragma unroll
        for (int m = 0; m < 50; m++) h1[m] += hk * sW1[k * 50 + m];
    }
    #pragma unroll
    for (int m = 0; m < 50; m++)
        h1[m] = fast_tanh(h1[m]) + h0[(m < 25) ? m : (m - 25)];

    float* out = g_tab + (size_t)(t * K_TAB + i) * 100;
    for (int c = 0; c < 2; c++) {
        float acc[50];
        #pragma unroll
        for (int m = 0; m < 50; m++) acc[m] = sB2[c * 50 + m];
        for (int k = 0; k < 50; k++) {
            float hk = h1[k];
            #pragma unroll
            for (int m = 0; m < 50; m++) acc[m] += hk * sW2[k * 100 + c * 50 + m];
        }
        #pragma unroll
        for (int m = 0; m < 50; m++)
            out[c * 50 + m] = fast_tanh(acc[m]) + h1[m];
    }
}

// ---------------------------------------------------------------------------
// Kernel 2: embed via table interpolation + xyz + DR. One block = atom.
// ---------------------------------------------------------------------------
__global__ void __launch_bounds__(256) embed_kernel(
    const float4* __restrict__ imdr,
    const int*    __restrict__ tmap,
    const float4* __restrict__ davg,
    const float4* __restrict__ dstd)
{
    __shared__ int    sK[200];      // knot*100 (pre-scaled row offset)
    __shared__ float  sF[200];      // fraction
    __shared__ float4 sRi4[200];
    __shared__ float  sP[1024];     // partials: [jh][d][128]
    __shared__ float  sXYZ[400];

    int tid = threadIdx.x;
    int a = blockIdx.x;
    int n = a & 1023;
    int t = tmap[n];

    if (tid < 200) {
        int j = tid;
        float4 im = imdr[(size_t)a * 200 + j];
        float r = im.x;
        float invr = (r > 1e-5f) ? (1.0f / r) : 1.0f;
        float u  = (r - 0.5f) * (1.0f / 5.5f);
        float u2 = u * u;
        float smid = invr * (u * u2 * (-6.0f * u2 + 15.0f * u - 10.0f) + 1.0f);
        float srij = 0.0f;
        if (r > 0.0f && r < 0.5f)        srij = invr;
        else if (r >= 0.5f && r < 6.0f)  srij = smid;
        bool msk = fabsf(r) > 1e-5f;
        float v0 = srij;
        float v1 = msk ? srij * im.y * invr : 0.0f;
        float v2 = msk ? srij * im.z * invr : 0.0f;
        float v3 = msk ? srij * im.w * invr : 0.0f;
        float4 da = davg[t * 200 + j];
        float4 ds = dstd[t * 200 + j];
        v0 = (v0 - da.x) / ds.x;
        v1 = (v1 - da.y) / ds.y;
        v2 = (v2 - da.z) / ds.z;
        v3 = (v3 - da.w) / ds.w;
        sRi4[j] = make_float4(v0, v1, v2, v3);

        float pos = (v0 - S_LO) * ((float)(K_TAB - 1) / (S_HI - S_LO));
        pos = fminf(fmaxf(pos, 0.0f), (float)(K_TAB - 1));
        float kf = floorf(pos);
        int k = (int)kf;
        if (k > K_TAB - 2) k = K_TAB - 2;
        sK[j] = k * 100;
        sF[j] = pos - (float)k;
    }
    __syncthreads();

    int jh = tid >> 7;
    int mslot = tid & 127;
    if (mslot < 100) {
        const float* tb = g_tab + (size_t)jh * K_TAB * 100 + mslot;  // nt = jh
        int j0 = jh * 100;
        float a0 = 0.0f, a1 = 0.0f, a2 = 0.0f, a3 = 0.0f;
        #pragma unroll 4
        for (int jj = 0; jj < 100; jj++) {
            int j = j0 + jj;
            int ko = sK[j];
            float f = sF[j];
            float4 ri = sRi4[j];
            float t0 = __ldg(tb + ko);
            float t1 = __ldg(tb + ko + 100);
            float g = fmaf(f, t1 - t0, t0);
            a0 = fmaf(ri.x, g, a0);
            a1 = fmaf(ri.y, g, a1);
            a2 = fmaf(ri.z, g, a2);
            a3 = fmaf(ri.w, g, a3);
        }
        sP[jh * 512 +   0 + mslot] = a0;
        sP[jh * 512 + 128 + mslot] = a1;
        sP[jh * 512 + 256 + mslot] = a2;
        sP[jh * 512 + 384 + mslot] = a3;
    }
    __syncthreads();

    for (int i = tid; i < 400; i += 256) {
        int d = i / 100, m = i - d * 100;
        sXYZ[d * 100 + m] =
            (sP[d * 128 + m] + sP[512 + d * 128 + m]) * (1.0f / 200.0f);
    }
    __syncthreads();

    for (int idx = tid; idx < 1600; idx += 256) {
        int m = idx >> 4, q = idx & 15;
        float s = 0.0f;
        #pragma unroll
        for (int d = 0; d < 4; d++)
            s += sXYZ[d * 100 + m] * sXYZ[d * 100 + q];
        g_DR[(size_t)a * 1600 + idx] = s;
    }
}

// ---------------------------------------------------------------------------
// Kernel 3: fitting net, f32x2 over row pairs (R12 per-column structure —
// the register-tile variants R13/R14 regressed). Block = 4 rows
// (4 same-type n x 1 batch) -> smem 33280 B -> 3 CTAs/SM (24 warps).
// Grid (258, 4).
// ---------------------------------------------------------------------------
__global__ void __launch_bounds__(256, 3) fit_kernel(
    const int*   __restrict__ tmap,
    const float* __restrict__ fW0, const float* __restrict__ fb0,
    const float* __restrict__ fW1, const float* __restrict__ fb1,
    const float* __restrict__ fW2, const float* __restrict__ fb2,
    const float* __restrict__ fWf, const float* __restrict__ fbf,
    float* __restrict__ out)
{
    extern __shared__ float sm[];
    float* sDR2 = sm;            // pair p(0..1): [p*3200 + 2k + parity]
    float* sHa2 = sm + 6400;     // pair p: [p*480 + 2k + parity]
    float* sHb2 = sm + 7360;
    // total 8320 floats = 33280 B

    int tid = threadIdx.x;
    int g = blockIdx.x;
    int b = blockIdx.y;          // batch
    int nn[4];
    nn[0] = g_sorted_n[g * 4 + 0];
    nn[1] = g_sorted_n[g * 4 + 1];
    nn[2] = g_sorted_n[g * 4 + 2];
    nn[3] = g_sorted_n[g * 4 + 3];
    int firstn = (nn[0] >= 0) ? nn[0] : (nn[1] >= 0) ? nn[1]
               : (nn[2] >= 0) ? nn[2] : nn[3];
    if (firstn < 0) return;
    int t = tmap[firstn];

    // stage 4 rows of DR, row-pair interleaved (row = n-slot s)
    for (int idx = tid; idx < 4 * 1600; idx += 256) {
        int row = idx / 1600;
        int k   = idx - row * 1600;
        int nv  = nn[row];
        float v = (nv >= 0) ? g_DR[((size_t)(b * 1024 + nv)) * 1600 + k] : 0.0f;
        sDR2[(row >> 1) * 3200 + 2 * k + (row & 1)] = v;
    }
    __syncthreads();

    int m = tid;
    const float* W0 = fW0 + (size_t)t * 1600 * 240;
    const float* W1 = fW1 + t * 240 * 240;
    const float* W2 = fW2 + t * 240 * 240;

    ull  accp[2];
    float prevA[4];
    float prevB[4];

    // layer0: 1600 -> 240
    if (m < 240) {
        float b0v = fb0[t * 240 + m];
        ull b0p = pack2(b0v, b0v);
        #pragma unroll
        for (int p = 0; p < 2; p++) accp[p] = b0p;
        for (int k = 0; k < 1600; k += 4) {
            float w0 = W0[(k + 0) * 240 + m];
            float w1 = W0[(k + 1) * 240 + m];
            float w2v = W0[(k + 2) * 240 + m];
            float w3 = W0[(k + 3) * 240 + m];
            ull wp0 = pack2(w0, w0), wp1 = pack2(w1, w1);
            ull wp2 = pack2(w2v, w2v), wp3 = pack2(w3, w3);
            #pragma unroll
            for (int p = 0; p < 2; p++) {
                const ulonglong2* dd = (const ulonglong2*)(sDR2 + p * 3200 + 2 * k);
                ulonglong2 dA = dd[0];
                ulonglong2 dB = dd[1];
                accp[p] = ffma2(dA.x, wp0, accp[p]);
                accp[p] = ffma2(dA.y, wp1, accp[p]);
                accp[p] = ffma2(dB.x, wp2, accp[p]);
                accp[p] = ffma2(dB.y, wp3, accp[p]);
            }
        }
        #pragma unroll
        for (int p = 0; p < 2; p++) {
            float lo, hi;
            unpack2(accp[p], lo, hi);
            float a0 = fast_tanh(lo), a1 = fast_tanh(hi);
            prevA[2 * p] = a0; prevA[2 * p + 1] = a1;
            *(ull*)(sHa2 + p * 480 + 2 * m) = pack2(a0, a1);
        }
    }
    __syncthreads();

    // layer1: 240 -> 240, resnet
    if (m < 240) {
        float b1v = fb1[t * 240 + m];
        ull b1p = pack2(b1v, b1v);
        #pragma unroll
        for (int p = 0; p < 2; p++) accp[p] = b1p;
        for (int k = 0; k < 240; k += 4) {
            float w0 = W1[(k + 0) * 240 + m];
            float w1 = W1[(k + 1) * 240 + m];
            float w2v = W1[(k + 2) * 240 + m];
            float w3 = W1[(k + 3) * 240 + m];
            ull wp0 = pack2(w0, w0), wp1 = pack2(w1, w1);
            ull wp2 = pack2(w2v, w2v), wp3 = pack2(w3, w3);
            #pragma unroll
            for (int p = 0; p < 2; p++) {
                const ulonglong2* hh = (const ulonglong2*)(sHa2 + p * 480 + 2 * k);
                ulonglong2 hA = hh[0];
                ulonglong2 hB = hh[1];
                accp[p] = ffma2(hA.x, wp0, accp[p]);
                accp[p] = ffma2(hA.y, wp1, accp[p]);
                accp[p] = ffma2(hB.x, wp2, accp[p]);
                accp[p] = ffma2(hB.y, wp3, accp[p]);
            }
        }
        #pragma unroll
        for (int p = 0; p < 2; p++) {
            float lo, hi;
            unpack2(accp[p], lo, hi);
            float a0 = fast_tanh(lo) + prevA[2 * p];
            float a1 = fast_tanh(hi) + prevA[2 * p + 1];
            prevB[2 * p] = a0; prevB[2 * p + 1] = a1;
            *(ull*)(sHb2 + p * 480 + 2 * m) = pack2(a0, a1);
        }
    }
    __syncthreads();

    // layer2: 240 -> 240, resnet; result into sHa2 (its reads are done)
    if (m < 240) {
        float b2v = fb2[t * 240 + m];
        ull b2p = pack2(b2v, b2v);
        #pragma unroll
        for (int p = 0; p < 2; p++) accp[p] = b2p;
        for (int k = 0; k < 240; k += 4) {
            float w0 = W2[(k + 0) * 240 + m];
            float w1 = W2[(k + 1) * 240 + m];
            float w2v = W2[(k + 2) * 240 + m];
            float w3 = W2[(k + 3) * 240 + m];
            ull wp0 = pack2(w0, w0), wp1 = pack2(w1, w1);
            ull wp2 = pack2(w2v, w2v), wp3 = pack2(w3, w3);
            #pragma unroll
            for (int p = 0; p < 2; p++) {
                const ulonglong2* hh = (const ulonglong2*)(sHb2 + p * 480 + 2 * k);
                ulonglong2 hA = hh[0];
                ulonglong2 hB = hh[1];
                accp[p] = ffma2(hA.x, wp0, accp[p]);
                accp[p] = ffma2(hA.y, wp1, accp[p]);
                accp[p] = ffma2(hB.x, wp2, accp[p]);
                accp[p] = ffma2(hB.y, wp3, accp[p]);
            }
        }
        #pragma unroll
        for (int p = 0; p < 2; p++) {
            float lo, hi;
            unpack2(accp[p], lo, hi);
            float a0 = fast_tanh(lo) + prevB[2 * p];
            float a1 = fast_tanh(hi) + prevB[2 * p + 1];
            *(ull*)(sHa2 + p * 480 + 2 * m) = pack2(a0, a1);
        }
    }
    __syncthreads();

    // final: h @ fWf + fbf (4 rows)
    if (tid < 4) {
        int s = tid;
        int nv = nn[s];
        if (nv >= 0) {
            int p = s >> 1, par = s & 1;
            float e = fbf[t];
            const float* Wf = fWf + t * 240;
            float s0 = 0.0f;
            for (int k = 0; k < 240; k++)
                s0 += sHa2[p * 480 + 2 * k + par] * Wf[k];
            out[4 + b * 1024 + nv] = e + s0;
        }
    }
}

// ---------------------------------------------------------------------------
// Kernel 4: Etot = sum_n Ei (deterministic tree reduce, one block per batch)
// ---------------------------------------------------------------------------
__global__ void etot_kernel(float* __restrict__ out)
{
    __shared__ float red[256];
    int b = blockIdx.x, tid = threadIdx.x;
    float s = 0.0f;
    for (int i = tid; i < 1024; i += 256) s += out[4 + b * 1024 + i];
    red[tid] = s;
    __syncthreads();
    for (int off = 128; off > 0; off >>= 1) {
        if (tid < off) red[tid] += red[tid + off];
        __syncthreads();
    }
    if (tid == 0) out[b] = red[0];
}

// ---------------------------------------------------------------------------
extern "C" void kernel_launch(void* const* d_in, const int* in_sizes, int n_in,
                              void* d_out, int out_size)
{
    int off = (n_in >= 24) ? 0 : -1;   // nghost scalar may or may not materialize

    const int*    tmap = (const int*)   d_in[1];
    const float4* imdr = (const float4*)d_in[3];
    const float4* davg = (const float4*)d_in[5 + off];
    const float4* dstd = (const float4*)d_in[6 + off];
    const float*  tvec = (const float*) d_in[7 + off];
    const float*  tW0  = (const float*) d_in[8 + off];
    const float*  tb0  = (const float*) d_in[9 + off];
    const float*  eW0  = (const float*) d_in[10 + off];
    const float*  eb0  = (const float*) d_in[11 + off];
    const float*  eW1  = (const float*) d_in[12 + off];
    const float*  eb1  = (const float*) d_in[13 + off];
    const float*  eW2  = (const float*) d_in[14 + off];
    const float*  eb2  = (const float*) d_in[15 + off];
    const float*  fW0  = (const float*) d_in[16 + off];
    const float*  fb0  = (const float*) d_in[17 + off];
    const float*  fW1  = (const float*) d_in[18 + off];
    const float*  fb1  = (const float*) d_in[19 + off];
    const float*  fW2  = (const float*) d_in[20 + off];
    const float*  fb2  = (const float*) d_in[21 + off];
    const float*  fWf  = (const float*) d_in[22 + off];
    const float*  fbf  = (const float*) d_in[23 + off];
    float* out = (float*)d_out;

    cudaFuncSetAttribute(fit_kernel, cudaFuncAttributeMaxDynamicSharedMemorySize, 33280);

    sort_kernel<<<1, 1024>>>(tmap);
    build_tab_kernel<<<2 * K_TAB / 256, 256>>>(tvec, tW0, tb0, eW0, eb0,
                                               eW1, eb1, eW2, eb2);
    embed_kernel<<<4096, 256>>>(imdr, tmap, davg, dstd);
    fit_kernel<<<dim3(258, 4), 256, 33280>>>(tmap, fW0, fb0, fW1, fb1,
                                             fW2, fb2, fWf, fbf, out);
    etot_kernel<<<4, 256>>>(out);
}